// round 1
// baseline (speedup 1.0000x reference)
#include <cuda_runtime.h>
#include <cuda_bf16.h>

#define TT 2048
#define CC 8

// 128 MB scratch: texture transposed to [T, T, C] so one bilinear tap is 32
// contiguous bytes (1 L2 sector) instead of 8 scattered sectors.
__device__ float g_tex2[(size_t)CC * TT * TT];

typedef unsigned long long u64;

__device__ __forceinline__ u64 pk2(float a, float b) {
    u64 r; asm("mov.b64 %0, {%1, %2};" : "=l"(r) : "f"(a), "f"(b)); return r;
}
__device__ __forceinline__ void upk2(u64 v, float& a, float& b) {
    asm("mov.b64 {%0, %1}, %2;" : "=f"(a), "=f"(b) : "l"(v));
}
__device__ __forceinline__ u64 fma2(u64 a, u64 b, u64 c) {
    u64 d; asm("fma.rn.f32x2 %0, %1, %2, %3;" : "=l"(d) : "l"(a), "l"(b), "l"(c));
    return d;
}
__device__ __forceinline__ u64 relu2(u64 v) {
    float a, b; upk2(v, a, b);
    return pk2(fmaxf(a, 0.f), fmaxf(b, 0.f));
}
__device__ __forceinline__ float sigm(float x) {
    return 1.0f / (1.0f + __expf(-x));
}

// ---------------------------------------------------------------------------
// Pass 1: transpose [C, T, T] -> [T, T, C]. Reads coalesced per channel,
// writes 32B contiguous per texel.
// ---------------------------------------------------------------------------
__global__ void transpose_tex_kernel(const float* __restrict__ tex) {
    int idx = blockIdx.x * blockDim.x + threadIdx.x;   // over T*T texels
    float v[CC];
#pragma unroll
    for (int c = 0; c < CC; c++)
        v[c] = tex[(size_t)c * TT * TT + idx];
    float4* o = reinterpret_cast<float4*>(g_tex2 + (size_t)idx * CC);
    o[0] = make_float4(v[0], v[1], v[2], v[3]);
    o[1] = make_float4(v[4], v[5], v[6], v[7]);
}

// ---------------------------------------------------------------------------
// Bilinear sample of one (u,v) -> feat[8], using the [T,T,C] scratch.
// Matches grid_sample(bilinear, zeros, align_corners=True).
// ---------------------------------------------------------------------------
__device__ __forceinline__ void sample_one(float u, float v, float feat[CC]) {
    float x = (u + 1.0f) * 1023.5f;   // 0.5*(T-1) = 1023.5
    float y = (v + 1.0f) * 1023.5f;
    float x0f = floorf(x), y0f = floorf(y);
    float wx1 = x - x0f, wy1 = y - y0f;
    float wx0 = 1.0f - wx1, wy0 = 1.0f - wy1;
    int x0 = (int)x0f, y0 = (int)y0f;
    int x1 = x0 + 1,   y1 = y0 + 1;
    // zero-padding masks folded into the weights
    float ax0 = (x0 >= 0 && x0 <= TT - 1) ? wx0 : 0.0f;
    float ax1 = (x1 >= 0 && x1 <= TT - 1) ? wx1 : 0.0f;
    float ay0 = (y0 >= 0 && y0 <= TT - 1) ? wy0 : 0.0f;
    float ay1 = (y1 >= 0 && y1 <= TT - 1) ? wy1 : 0.0f;
    int x0c = min(max(x0, 0), TT - 1);
    int x1c = min(max(x1, 0), TT - 1);
    int y0c = min(max(y0, 0), TT - 1);
    int y1c = min(max(y1, 0), TT - 1);

    const float4* p00 = reinterpret_cast<const float4*>(g_tex2 + ((size_t)y0c * TT + x0c) * CC);
    const float4* p01 = reinterpret_cast<const float4*>(g_tex2 + ((size_t)y0c * TT + x1c) * CC);
    const float4* p10 = reinterpret_cast<const float4*>(g_tex2 + ((size_t)y1c * TT + x0c) * CC);
    const float4* p11 = reinterpret_cast<const float4*>(g_tex2 + ((size_t)y1c * TT + x1c) * CC);

    float4 t00a = p00[0], t00b = p00[1];
    float4 t01a = p01[0], t01b = p01[1];
    float4 t10a = p10[0], t10b = p10[1];
    float4 t11a = p11[0], t11b = p11[1];

    const float* t00 = reinterpret_cast<const float*>(&t00a); // t00a,t00b contiguous regs
    const float* t01 = reinterpret_cast<const float*>(&t01a);
    const float* t10 = reinterpret_cast<const float*>(&t10a);
    const float* t11 = reinterpret_cast<const float*>(&t11a);
    // NOTE: &t00a gives 4 floats; handle second half explicitly.
    const float* t00h = reinterpret_cast<const float*>(&t00b);
    const float* t01h = reinterpret_cast<const float*>(&t01b);
    const float* t10h = reinterpret_cast<const float*>(&t10b);
    const float* t11h = reinterpret_cast<const float*>(&t11b);

#pragma unroll
    for (int c = 0; c < 4; c++) {
        float v0 = ax0 * t00[c] + ax1 * t01[c];
        float v1 = ax0 * t10[c] + ax1 * t11[c];
        feat[c] = ay0 * v0 + ay1 * v1;
    }
#pragma unroll
    for (int c = 0; c < 4; c++) {
        float v0 = ax0 * t00h[c] + ax1 * t01h[c];
        float v1 = ax0 * t10h[c] + ax1 * t11h[c];
        feat[4 + c] = ay0 * v0 + ay1 * v1;
    }
}

// ---------------------------------------------------------------------------
// Pass 2: fused sample + MLP. 4 samples per thread, packed f32x2 MLP
// (2 samples per packed lane-pair), weights duplicated in shared as float2
// so one LDS.64 yields a broadcast-ready (w,w) pair.
// ---------------------------------------------------------------------------
__global__ __launch_bounds__(128)
void fused_kernel(const float* __restrict__ uv,
                  const float* __restrict__ vd,
                  float* __restrict__ out,
                  const float* __restrict__ W1, const float* __restrict__ b1,
                  const float* __restrict__ W2, const float* __restrict__ b2,
                  const float* __restrict__ W3, const float* __restrict__ b3) {
    __shared__ float2 sW1[16 * 11];
    __shared__ float2 sB1[16];
    __shared__ float2 sW2[16 * 16];
    __shared__ float2 sB2[16];
    __shared__ float2 sW3[3 * 16];
    __shared__ float2 sB3[3];

    int t = threadIdx.x;
    for (int i = t; i < 176; i += 128) { float w = W1[i]; sW1[i] = make_float2(w, w); }
    for (int i = t; i < 256; i += 128) { float w = W2[i]; sW2[i] = make_float2(w, w); }
    if (t < 48) { float w = W3[t]; sW3[t] = make_float2(w, w); }
    if (t < 16) { float w = b1[t]; sB1[t] = make_float2(w, w); }
    else if (t < 32) { float w = b2[t - 16]; sB2[t - 16] = make_float2(w, w); }
    else if (t < 35) { float w = b3[t - 32]; sB3[t - 32] = make_float2(w, w); }
    __syncthreads();

    int tid = blockIdx.x * blockDim.x + threadIdx.x;
    int base = tid * 4;   // 4 samples per thread

    // uv: 8 floats -> 2 float4 loads; viewdirs: 12 floats -> 3 float4 loads
    const float4* uv4 = reinterpret_cast<const float4*>(uv + (size_t)base * 2);
    float4 uvA = uv4[0];   // samples 0,1
    float4 uvB = uv4[1];   // samples 2,3
    const float4* vd4 = reinterpret_cast<const float4*>(vd + (size_t)base * 3);
    float4 vda = vd4[0], vdb = vd4[1], vdc = vd4[2];

    float f0[CC], f1[CC], f2[CC], f3[CC];
    sample_one(uvA.x, uvA.y, f0);
    sample_one(uvA.z, uvA.w, f1);
    sample_one(uvB.x, uvB.y, f2);
    sample_one(uvB.z, uvB.w, f3);

    // Pack inputs: pair0 = (sample0, sample1), pair1 = (sample2, sample3)
    u64 X0[11], X1[11];
#pragma unroll
    for (int c = 0; c < CC; c++) {
        X0[c] = pk2(f0[c], f1[c]);
        X1[c] = pk2(f2[c], f3[c]);
    }
    // viewdirs layout: [s0x s0y s0z s1x | s1y s1z s2x s2y | s2z s3x s3y s3z]
    X0[8]  = pk2(vda.x, vda.w);
    X0[9]  = pk2(vda.y, vdb.x);
    X0[10] = pk2(vda.z, vdb.y);
    X1[8]  = pk2(vdb.z, vdc.y);
    X1[9]  = pk2(vdb.w, vdc.z);
    X1[10] = pk2(vdc.x, vdc.w);

    // Layer 1: 11 -> 16, relu
    u64 H0[16], H1[16];
#pragma unroll
    for (int j = 0; j < 16; j++) {
        float2 bb = sB1[j];
        u64 a0 = pk2(bb.x, bb.y);
        u64 a1 = a0;
#pragma unroll
        for (int k = 0; k < 11; k++) {
            float2 wf = sW1[j * 11 + k];
            u64 w = pk2(wf.x, wf.y);
            a0 = fma2(w, X0[k], a0);
            a1 = fma2(w, X1[k], a1);
        }
        H0[j] = relu2(a0);
        H1[j] = relu2(a1);
    }

    // Layer 2: 16 -> 16, relu
    u64 G0[16], G1[16];
#pragma unroll
    for (int j = 0; j < 16; j++) {
        float2 bb = sB2[j];
        u64 a0 = pk2(bb.x, bb.y);
        u64 a1 = a0;
#pragma unroll
        for (int k = 0; k < 16; k++) {
            float2 wf = sW2[j * 16 + k];
            u64 w = pk2(wf.x, wf.y);
            a0 = fma2(w, H0[k], a0);
            a1 = fma2(w, H1[k], a1);
        }
        G0[j] = relu2(a0);
        G1[j] = relu2(a1);
    }

    // Layer 3: 16 -> 3, sigmoid
    float rgb[12];
#pragma unroll
    for (int j = 0; j < 3; j++) {
        float2 bb = sB3[j];
        u64 a0 = pk2(bb.x, bb.y);
        u64 a1 = a0;
#pragma unroll
        for (int k = 0; k < 16; k++) {
            float2 wf = sW3[j * 16 + k];
            u64 w = pk2(wf.x, wf.y);
            a0 = fma2(w, G0[k], a0);
            a1 = fma2(w, G1[k], a1);
        }
        float s0, s1, s2, s3;
        upk2(a0, s0, s1);
        upk2(a1, s2, s3);
        rgb[0 * 3 + j] = sigm(s0);
        rgb[1 * 3 + j] = sigm(s1);
        rgb[2 * 3 + j] = sigm(s2);
        rgb[3 * 3 + j] = sigm(s3);
    }

    // 12 contiguous floats at out + base*3 (48B, 16B-aligned) -> 3 stg.128
    float4* o4 = reinterpret_cast<float4*>(out + (size_t)base * 3);
    o4[0] = make_float4(rgb[0], rgb[1], rgb[2],  rgb[3]);
    o4[1] = make_float4(rgb[4], rgb[5], rgb[6],  rgb[7]);
    o4[2] = make_float4(rgb[8], rgb[9], rgb[10], rgb[11]);
}

extern "C" void kernel_launch(void* const* d_in, const int* in_sizes, int n_in,
                              void* d_out, int out_size) {
    const float* uv  = (const float*)d_in[0];
    const float* vd  = (const float*)d_in[1];
    const float* tex = (const float*)d_in[2];
    const float* W1  = (const float*)d_in[3];
    const float* b1  = (const float*)d_in[4];
    const float* W2  = (const float*)d_in[5];
    const float* b2  = (const float*)d_in[6];
    const float* W3  = (const float*)d_in[7];
    const float* b3  = (const float*)d_in[8];
    float* out = (float*)d_out;

    int B = in_sizes[0] / 2;          // uv has B*2 elements

    // Pass 1: transpose texture into [T,T,C] scratch
    transpose_tex_kernel<<<(TT * TT) / 256, 256>>>(tex);

    // Pass 2: fused gather + MLP, 4 samples/thread
    int nthreads = B / 4;
    fused_kernel<<<nthreads / 128, 128>>>(uv, vd, out, W1, b1, W2, b2, W3, b3);
}

// round 4
// speedup vs baseline: 1.3770x; 1.3770x over previous
#include <cuda_runtime.h>
#include <cuda_fp16.h>

#define TT 2048
#define CC 8
#define QN 1025            // quadrant size: x,y in [1023, 2047]
#define QS 1025            // row stride in texels

// 16.8 MB scratch: quadrant of texture, transposed to [y][x][c], fp16.
// One bilinear tap = 16 contiguous bytes = one LDG.128, L2-resident.
__device__ __half2 g_texh[(size_t)QS * QN * 4];

typedef unsigned long long u64;

__device__ __forceinline__ u64 pk2(float a, float b) {
    u64 r; asm("mov.b64 %0, {%1, %2};" : "=l"(r) : "f"(a), "f"(b)); return r;
}
__device__ __forceinline__ void upk2(u64 v, float& a, float& b) {
    asm("mov.b64 {%0, %1}, %2;" : "=f"(a), "=f"(b) : "l"(v));
}
__device__ __forceinline__ u64 fma2(u64 a, u64 b, u64 c) {
    u64 d; asm("fma.rn.f32x2 %0, %1, %2, %3;" : "=l"(d) : "l"(a), "l"(b), "l"(c));
    return d;
}
__device__ __forceinline__ u64 mul2(u64 a, u64 b) {
    u64 d; asm("mul.rn.f32x2 %0, %1, %2;" : "=l"(d) : "l"(a), "l"(b));
    return d;
}
__device__ __forceinline__ u64 relu2(u64 v) {
    float a, b; upk2(v, a, b);
    return pk2(fmaxf(a, 0.f), fmaxf(b, 0.f));
}
__device__ __forceinline__ float sigm(float x) {
    return 1.0f / (1.0f + __expf(-x));
}

// ---------------------------------------------------------------------------
// Pass 1: quadrant transpose+convert [C,T,T] fp32 -> [QN,QN,C] fp16.
// ---------------------------------------------------------------------------
__global__ void transpose_q(const float* __restrict__ tex) {
    int x = blockIdx.x * 128 + threadIdx.x;
    int y = blockIdx.y;
    if (x >= QN) return;
    size_t src = (size_t)(1023 + y) * TT + 1023 + x;
    float v[CC];
#pragma unroll
    for (int c = 0; c < CC; c++)
        v[c] = tex[(size_t)c * TT * TT + src];
    __half2 h0 = __floats2half2_rn(v[0], v[1]);
    __half2 h1 = __floats2half2_rn(v[2], v[3]);
    __half2 h2 = __floats2half2_rn(v[4], v[5]);
    __half2 h3 = __floats2half2_rn(v[6], v[7]);
    uint4 w;
    w.x = *(unsigned*)&h0; w.y = *(unsigned*)&h1;
    w.z = *(unsigned*)&h2; w.w = *(unsigned*)&h3;
    *reinterpret_cast<uint4*>(g_texh + ((size_t)y * QS + x) * 4) = w;
}

// ---------------------------------------------------------------------------
// Bilinear sample (align_corners=True, zero padding; uv in [0,1) so all taps
// are in the stored quadrant and padding masks are always 1).
// ---------------------------------------------------------------------------
__device__ __forceinline__ void sample_one(float u, float v, float f[CC]) {
    float x = fmaf(u, 1023.5f, 1023.5f);   // (u+1)*0.5*(T-1)
    float y = fmaf(v, 1023.5f, 1023.5f);
    int x0i = __float2int_rd(x);
    int y0i = __float2int_rd(y);
    float wx1 = x - (float)x0i;
    float wy1 = y - (float)y0i;
    float wx0 = 1.0f - wx1, wy0 = 1.0f - wy1;
    int lx0 = min(max(x0i - 1023, 0), QN - 1);
    int ly0 = min(max(y0i - 1023, 0), QN - 1);
    int lx1 = min(lx0 + 1, QN - 1);
    int ly1 = min(ly0 + 1, QN - 1);

    uint4 t00 = *reinterpret_cast<const uint4*>(g_texh + ((size_t)ly0 * QS + lx0) * 4);
    uint4 t01 = *reinterpret_cast<const uint4*>(g_texh + ((size_t)ly0 * QS + lx1) * 4);
    uint4 t10 = *reinterpret_cast<const uint4*>(g_texh + ((size_t)ly1 * QS + lx0) * 4);
    uint4 t11 = *reinterpret_cast<const uint4*>(g_texh + ((size_t)ly1 * QS + lx1) * 4);

    float w00 = wy0 * wx0, w01 = wy0 * wx1, w10 = wy1 * wx0, w11 = wy1 * wx1;
    u64 W00 = pk2(w00, w00), W01 = pk2(w01, w01);
    u64 W10 = pk2(w10, w10), W11 = pk2(w11, w11);

    const __half2* h00 = reinterpret_cast<const __half2*>(&t00);
    const __half2* h01 = reinterpret_cast<const __half2*>(&t01);
    const __half2* h10 = reinterpret_cast<const __half2*>(&t10);
    const __half2* h11 = reinterpret_cast<const __half2*>(&t11);

#pragma unroll
    for (int p = 0; p < 4; p++) {
        float2 a = __half22float2(h00[p]);
        float2 b = __half22float2(h01[p]);
        float2 c = __half22float2(h10[p]);
        float2 d = __half22float2(h11[p]);
        u64 acc = mul2(W00, pk2(a.x, a.y));
        acc = fma2(W01, pk2(b.x, b.y), acc);
        acc = fma2(W10, pk2(c.x, c.y), acc);
        acc = fma2(W11, pk2(d.x, d.y), acc);
        upk2(acc, f[2 * p], f[2 * p + 1]);
    }
}

// ---------------------------------------------------------------------------
// Pass 2: fused sample + MLP. 4 samples/thread, 2 packed f32x2 pairs.
// Weights in shared as (w_k, w_k, w_{k+1}, w_{k+1}) float4 so one LDS.128
// feeds 4 fma2 instructions.
// ---------------------------------------------------------------------------
__global__ __launch_bounds__(128)
void fused_kernel(const float* __restrict__ uv,
                  const float* __restrict__ vd,
                  float* __restrict__ out,
                  const float* __restrict__ W1, const float* __restrict__ b1,
                  const float* __restrict__ W2, const float* __restrict__ b2,
                  const float* __restrict__ W3, const float* __restrict__ b3) {
    __shared__ float4 sW1[16 * 6];   // K padded 11 -> 12
    __shared__ float4 sW2[16 * 8];
    __shared__ float4 sW3[3 * 8];
    __shared__ float2 sB1[16], sB2[16], sB3[3];

    int t = threadIdx.x;
    // layer1 weights: slot (j, kk) holds (W1[j,2kk],W1[j,2kk],W1[j,2kk+1],W1[j,2kk+1]), 0-pad k>=11
    if (t < 96) {
        int j = t / 6, kk = t % 6;
        int k0 = 2 * kk, k1 = 2 * kk + 1;
        float wa = (k0 < 11) ? W1[j * 11 + k0] : 0.0f;
        float wb = (k1 < 11) ? W1[j * 11 + k1] : 0.0f;
        sW1[t] = make_float4(wa, wa, wb, wb);
    }
    {
        int i = t;  // 128 slots for sW2
        int j = i / 8, kk = i % 8;
        float wa = W2[j * 16 + 2 * kk];
        float wb = W2[j * 16 + 2 * kk + 1];
        sW2[i] = make_float4(wa, wa, wb, wb);
    }
    if (t < 24) {
        int j = t / 8, kk = t % 8;
        float wa = W3[j * 16 + 2 * kk];
        float wb = W3[j * 16 + 2 * kk + 1];
        sW3[t] = make_float4(wa, wa, wb, wb);
    }
    if (t < 16)      { float w = b1[t];      sB1[t]      = make_float2(w, w); }
    else if (t < 32) { float w = b2[t - 16]; sB2[t - 16] = make_float2(w, w); }
    else if (t < 35) { float w = b3[t - 32]; sB3[t - 32] = make_float2(w, w); }
    __syncthreads();

    int tid = blockIdx.x * blockDim.x + threadIdx.x;
    int base = tid * 4;

    const float4* uv4 = reinterpret_cast<const float4*>(uv) + (size_t)tid * 2;
    float4 uvA = uv4[0];   // samples 0,1
    float4 uvB = uv4[1];   // samples 2,3
    const float4* vd4 = reinterpret_cast<const float4*>(vd) + (size_t)tid * 3;
    float4 vda = vd4[0], vdb = vd4[1], vdc = vd4[2];

    float f0[CC], f1[CC], f2[CC], f3[CC];
    sample_one(uvA.x, uvA.y, f0);
    sample_one(uvA.z, uvA.w, f1);
    sample_one(uvB.x, uvB.y, f2);
    sample_one(uvB.z, uvB.w, f3);

    // Pack inputs: X0 = (s0,s1), X1 = (s2,s3); index 11 is zero pad.
    u64 X0[12], X1[12];
#pragma unroll
    for (int c = 0; c < CC; c++) {
        X0[c] = pk2(f0[c], f1[c]);
        X1[c] = pk2(f2[c], f3[c]);
    }
    X0[8]  = pk2(vda.x, vda.w);
    X0[9]  = pk2(vda.y, vdb.x);
    X0[10] = pk2(vda.z, vdb.y);
    X1[8]  = pk2(vdb.z, vdc.y);
    X1[9]  = pk2(vdb.w, vdc.z);
    X1[10] = pk2(vdc.x, vdc.w);
    X0[11] = pk2(0.0f, 0.0f);
    X1[11] = X0[11];

    // Layer 1: 12(pad) -> 16, relu
    u64 H0[16], H1[16];
#pragma unroll
    for (int j = 0; j < 16; j++) {
        float2 bb = sB1[j];
        u64 a0 = pk2(bb.x, bb.y);
        u64 a1 = a0;
#pragma unroll
        for (int kk = 0; kk < 6; kk++) {
            float4 w = sW1[j * 6 + kk];
            u64 wA = pk2(w.x, w.y), wB = pk2(w.z, w.w);
            a0 = fma2(wA, X0[2 * kk], a0);
            a1 = fma2(wA, X1[2 * kk], a1);
            a0 = fma2(wB, X0[2 * kk + 1], a0);
            a1 = fma2(wB, X1[2 * kk + 1], a1);
        }
        H0[j] = relu2(a0);
        H1[j] = relu2(a1);
    }

    // Layer 2: 16 -> 16, relu
    u64 G0[16], G1[16];
#pragma unroll
    for (int j = 0; j < 16; j++) {
        float2 bb = sB2[j];
        u64 a0 = pk2(bb.x, bb.y);
        u64 a1 = a0;
#pragma unroll
        for (int kk = 0; kk < 8; kk++) {
            float4 w = sW2[j * 8 + kk];
            u64 wA = pk2(w.x, w.y), wB = pk2(w.z, w.w);
            a0 = fma2(wA, H0[2 * kk], a0);
            a1 = fma2(wA, H1[2 * kk], a1);
            a0 = fma2(wB, H0[2 * kk + 1], a0);
            a1 = fma2(wB, H1[2 * kk + 1], a1);
        }
        G0[j] = relu2(a0);
        G1[j] = relu2(a1);
    }

    // Layer 3: 16 -> 3, sigmoid
    float rgb[12];
#pragma unroll
    for (int j = 0; j < 3; j++) {
        float2 bb = sB3[j];
        u64 a0 = pk2(bb.x, bb.y);
        u64 a1 = a0;
#pragma unroll
        for (int kk = 0; kk < 8; kk++) {
            float4 w = sW3[j * 8 + kk];
            u64 wA = pk2(w.x, w.y), wB = pk2(w.z, w.w);
            a0 = fma2(wA, G0[2 * kk], a0);
            a1 = fma2(wA, G1[2 * kk], a1);
            a0 = fma2(wB, G0[2 * kk + 1], a0);
            a1 = fma2(wB, G1[2 * kk + 1], a1);
        }
        float s0, s1, s2, s3;
        upk2(a0, s0, s1);
        upk2(a1, s2, s3);
        rgb[0 * 3 + j] = sigm(s0);
        rgb[1 * 3 + j] = sigm(s1);
        rgb[2 * 3 + j] = sigm(s2);
        rgb[3 * 3 + j] = sigm(s3);
    }

    float4* o4 = reinterpret_cast<float4*>(out + (size_t)base * 3);
    o4[0] = make_float4(rgb[0], rgb[1], rgb[2],  rgb[3]);
    o4[1] = make_float4(rgb[4], rgb[5], rgb[6],  rgb[7]);
    o4[2] = make_float4(rgb[8], rgb[9], rgb[10], rgb[11]);
}

extern "C" void kernel_launch(void* const* d_in, const int* in_sizes, int n_in,
                              void* d_out, int out_size) {
    const float* uv  = (const float*)d_in[0];
    const float* vd  = (const float*)d_in[1];
    const float* tex = (const float*)d_in[2];
    const float* W1  = (const float*)d_in[3];
    const float* b1  = (const float*)d_in[4];
    const float* W2  = (const float*)d_in[5];
    const float* b2  = (const float*)d_in[6];
    const float* W3  = (const float*)d_in[7];
    const float* b3  = (const float*)d_in[8];
    float* out = (float*)d_out;

    int B = in_sizes[0] / 2;

    transpose_q<<<dim3((QN + 127) / 128, QN), 128>>>(tex);

    int nthreads = B / 4;
    fused_kernel<<<nthreads / 128, 128>>>(uv, vd, out, W1, b1, W2, b2, W3, b3);
}